// round 16
// baseline (speedup 1.0000x reference)
#include <cuda_runtime.h>
#include <cstdint>

// y[N] = x[N,H] @ w[H] + bias,  w[h] = FP4_TABLE[codes[h]] * absmax[h>>6]
// N = 32768, H = 4096.
//
// R14 conclusion: the streaming GEMV is pinned at ~82.7us / 6.5TB/s = the
// LTS service ceiling (~6300 B/cyc, path-independent) across every variant.
// Only remaining cost: the dequant pre-kernel + extra graph node (~1.5-3us).
// R15/R16: single fused kernel — dequant inline via warp-shuffle table
// lookup (lane l holds tab[l&15]; w = shfl(tab, code) * absmax). codes are
// L1-resident like g_w was; zero DRAM delta, ~9 extra issue slots per float4
// against 4x issue headroom. (R15 run was an infra failure; re-land.)

#define H_DIM 4096
#define RPB   8                      // rows per block, 1 per warp
#define THREADS (RPB * 32)

__device__ __constant__ float c_fp4_tab[16] = {
    0.0f, 0.0052083333f, 0.6666667f, 1.0f, 0.3333333f, 0.5f, 0.16666667f, 0.25f,
    -0.0f, -0.0052083333f, -0.6666667f, -1.0f, -0.3333333f, -0.5f, -0.16666667f, -0.25f
};

__global__ __launch_bounds__(THREADS)
void fp4_gemv_fused_kernel(const float* __restrict__ x,
                           const int*   __restrict__ codes,
                           const float* __restrict__ absmax,
                           const float* __restrict__ bias,
                           float*       __restrict__ y,
                           int N)
{
    const int warp = threadIdx.x >> 5;
    const int lane = threadIdx.x & 31;
    const int row  = blockIdx.x * RPB + warp;
    if (row >= N) return;             // warp-uniform; never taken for N=32768

    // Lanes 0..15 (and 16..31, duplicated) hold the fp4 table; per-element
    // dequant is then one shfl.idx (code in [0,16)).
    const float tabv = c_fp4_tab[lane & 15];

    const float4* __restrict__ xr =
        reinterpret_cast<const float4*>(x + (size_t)row * H_DIM);
    const int4*   __restrict__ cd = reinterpret_cast<const int4*>(codes);
    const float b = __ldg(bias);

    // 1024 float4 per row; 32 per lane as 4 groups of 8 (proven R8 shape).
    float acc0 = 0.0f, acc1 = 0.0f;

    #pragma unroll
    for (int g = 0; g < 4; g++) {
        float4 xv[8];
        #pragma unroll
        for (int j = 0; j < 8; j++) {
            xv[j] = __ldcs(&xr[g * 256 + j * 32 + lane]);   // read-once x stream
        }
        #pragma unroll
        for (int j = 0; j < 8; j++) {
            const int idx = g * 256 + j * 32 + lane;        // float4 index
            // 4 codes for this float4 (16KB total, L1-resident after row 1).
            int4  c  = __ldg(&cd[idx]);
            // elements 4*idx..4*idx+3 share one 64-element block scale.
            float am = __ldg(&absmax[idx >> 4]);

            float w0 = __shfl_sync(0xFFFFFFFFu, tabv, c.x & 15) * am;
            float w1 = __shfl_sync(0xFFFFFFFFu, tabv, c.y & 15) * am;
            float w2 = __shfl_sync(0xFFFFFFFFu, tabv, c.z & 15) * am;
            float w3 = __shfl_sync(0xFFFFFFFFu, tabv, c.w & 15) * am;

            acc0 = fmaf(xv[j].x, w0, acc0);
            acc1 = fmaf(xv[j].y, w1, acc1);
            acc0 = fmaf(xv[j].z, w2, acc0);
            acc1 = fmaf(xv[j].w, w3, acc1);
        }
    }
    float acc = acc0 + acc1;

    #pragma unroll
    for (int off = 16; off > 0; off >>= 1)
        acc += __shfl_xor_sync(0xFFFFFFFFu, acc, off);

    if (lane == 0)
        y[row] = acc + b;
}

extern "C" void kernel_launch(void* const* d_in, const int* in_sizes, int n_in,
                              void* d_out, int out_size)
{
    const float* x      = (const float*)d_in[0];   // [N, H] fp32
    const int*   codes  = (const int*)  d_in[1];   // [1, H] int32
    const float* absmax = (const float*)d_in[2];   // [1, H/64] fp32
    const float* bias   = (const float*)d_in[3];   // [1] fp32
    float*       y      = (float*)d_out;           // [N, 1] fp32

    const int N = in_sizes[0] / H_DIM;             // 32768
    const int grid = (N + RPB - 1) / RPB;          // 4096

    fp4_gemv_fused_kernel<<<grid, THREADS>>>(x, codes, absmax, bias, y, N);
}

// round 17
// speedup vs baseline: 1.0510x; 1.0510x over previous
#include <cuda_runtime.h>
#include <cstdint>

// y[N] = x[N,H] @ w[H] + bias,  w[h] = FP4_TABLE[codes[h]] * absmax[h>>6]
// N = 32768, H = 4096.
//
// R16 post-mortem: inline dequant slowed the streaming body (88.3us) — fusion
// dead. Champion remains the two-kernel R8 shape (GEMV 82.7us @ ~6.5TB/s =
// service ceiling). R17: hide the dequant node with PDL; GEMV issues its
// first x-load batch (independent of g_w) BEFORE gridDependencySynchronize,
// overlapping dequant execution with the GEMV's own first-load latency.

#define H_DIM 4096
#define RPB   8                      // rows per block, 1 per warp
#define THREADS (RPB * 32)

__device__ float g_w[H_DIM];         // dequantized weight scratch

__device__ __constant__ float c_fp4_tab[16] = {
    0.0f, 0.0052083333f, 0.6666667f, 1.0f, 0.3333333f, 0.5f, 0.16666667f, 0.25f,
    -0.0f, -0.0052083333f, -0.6666667f, -1.0f, -0.3333333f, -0.5f, -0.16666667f, -0.25f
};

__global__ void fp4_dequant_kernel(const int* __restrict__ codes,
                                   const float* __restrict__ absmax)
{
    int i = blockIdx.x * blockDim.x + threadIdx.x;
    if (i < H_DIM)
        g_w[i] = c_fp4_tab[codes[i] & 15] * absmax[i >> 6];
    __threadfence();                              // publish g_w
    cudaTriggerProgrammaticLaunchCompletion();    // release dependent GEMV
}

__global__ __launch_bounds__(THREADS)
void fp4_gemv_kernel(const float* __restrict__ x,
                     const float* __restrict__ bias,
                     float*       __restrict__ y,
                     int N)
{
    const int warp = threadIdx.x >> 5;
    const int lane = threadIdx.x & 31;
    const int row  = blockIdx.x * RPB + warp;
    if (row >= N) return;             // never taken for N=32768 (grid*RPB==N)

    const float4* __restrict__ xr =
        reinterpret_cast<const float4*>(x + (size_t)row * H_DIM);
    const float4* __restrict__ wr = reinterpret_cast<const float4*>(g_w);

    // Group 0 x-loads are independent of g_w: issue them BEFORE the PDL sync
    // so dequant execution overlaps our first-load latency.
    float4 xv[8];
    #pragma unroll
    for (int j = 0; j < 8; j++)
        xv[j] = __ldcs(&xr[j * 32 + lane]);

    cudaGridDependencySynchronize();   // g_w now valid

    const float b = __ldg(bias);
    float acc0 = 0.0f, acc1 = 0.0f;

    #pragma unroll
    for (int g = 0; g < 4; g++) {
        #pragma unroll
        for (int j = 0; j < 8; j++) {
            float4 wv = __ldg(&wr[g * 256 + j * 32 + lane]); // L1-resident 16KB
            acc0 = fmaf(xv[j].x, wv.x, acc0);
            acc1 = fmaf(xv[j].y, wv.y, acc1);
            acc0 = fmaf(xv[j].z, wv.z, acc0);
            acc1 = fmaf(xv[j].w, wv.w, acc1);
        }
        // Prefetch next group's x while this group's FMAs retire.
        if (g < 3) {
            #pragma unroll
            for (int j = 0; j < 8; j++)
                xv[j] = __ldcs(&xr[(g + 1) * 256 + j * 32 + lane]);
        }
    }
    float acc = acc0 + acc1;

    #pragma unroll
    for (int off = 16; off > 0; off >>= 1)
        acc += __shfl_xor_sync(0xFFFFFFFFu, acc, off);

    if (lane == 0)
        y[row] = acc + b;
}

extern "C" void kernel_launch(void* const* d_in, const int* in_sizes, int n_in,
                              void* d_out, int out_size)
{
    const float* x      = (const float*)d_in[0];   // [N, H] fp32
    const int*   codes  = (const int*)  d_in[1];   // [1, H] int32
    const float* absmax = (const float*)d_in[2];   // [1, H/64] fp32
    const float* bias   = (const float*)d_in[3];   // [1] fp32
    float*       y      = (float*)d_out;           // [N, 1] fp32

    const int N = in_sizes[0] / H_DIM;             // 32768

    fp4_dequant_kernel<<<(H_DIM + 255) / 256, 256>>>(codes, absmax);

    // GEMV with programmatic (PDL) dependency on the dequant kernel.
    cudaLaunchConfig_t cfg = {};
    cfg.gridDim  = dim3((N + RPB - 1) / RPB);      // 4096
    cfg.blockDim = dim3(THREADS);
    cfg.stream   = 0;
    cudaLaunchAttribute attr;
    attr.id = cudaLaunchAttributeProgrammaticStreamSerialization;
    attr.val.programmaticStreamSerializationAllowed = 1;
    cfg.attrs = &attr;
    cfg.numAttrs = 1;
    cudaLaunchKernelEx(&cfg, fp4_gemv_kernel, x, bias, y, N);
}